// round 6
// baseline (speedup 1.0000x reference)
#include <cuda_runtime.h>
#include <cuda_bf16.h>
#include <math_constants.h>

#define CC 64
#define HH 100
#define WW 252
#define KK 5
#define LL 5
#define BB 2
#define CPT 8
#define MAX_IMGS (LL * KK)
#define TPB 256
#define HWB (HH * WW * 4)          // channel stride in bytes

__global__ __launch_bounds__(TPB, 5)
void raindrop_fuse_kernel(const float* __restrict__ x,
                          const float* __restrict__ ptm,
                          const int*   __restrict__ record_len,
                          float*       __restrict__ out) {
    constexpr int HW = HH * WW;
    constexpr float S = 1.6f;  // DOWNSAMPLE * VOXEL
    const unsigned FULL = 0xffffffffu;

    const int b   = blockIdx.z;
    const int cg  = blockIdx.y;
    const int pix0 = blockIdx.x * TPB + threadIdx.x;
    const int lane = threadIdx.x & 31;

    __shared__ float th[MAX_IMGS][6];

    const int N       = record_len[b];
    const int numImgs = N * KK;
    const int start   = (b == 0) ? 0 : record_len[0] * KK;

    // theta' folds the reference `mult` scaling AND the grid->pixel transform.
    if (threadIdx.x < numImgs * 6) {
        const int idx = threadIdx.x;
        const int n = idx / 6, e = idx % 6;
        const int l = n / KK, k = n % KK;
        const int i = e / 3, j = e % 3;
        const int jj = (j == 2) ? 3 : j;
        const float mult[2][3] = {
            {1.0f, (float)HH / (float)WW, 2.0f / (S * WW)},
            {(float)WW / (float)HH, 1.0f, 2.0f / (S * HH)}
        };
        const float halfdim = (i == 0) ? ((float)WW * 0.5f) : ((float)HH * 0.5f);
        float v = ptm[((((b * LL) + l) * KK + k) * 4 + i) * 4 + jj] * mult[i][j];
        v *= halfdim;
        if (j == 2) v += halfdim - 0.5f;
        th[n][e] = v;
    }
    __syncthreads();

    // No early return (full-mask shuffles below). Clamp and predicate the store.
    const bool active = (pix0 < HW);
    const int pix = active ? pix0 : (HW - 1);

    const int h = pix / WW;
    const int w = pix - h * WW;
    const float gx = (2.0f * (float)w + 1.0f) * (1.0f / (float)WW) - 1.0f;
    const float gy = (2.0f * (float)h + 1.0f) * (1.0f / (float)HH) - 1.0f;

    float acc[CPT];
#pragma unroll
    for (int c = 0; c < CPT; c++) acc[c] = -CUDART_INF_F;
    float oobVal = -CUDART_INF_F;

    const char* pimg = (const char*)x + (size_t)(start * CC + cg * CPT) * (size_t)(HW * 4);

    for (int n = 0; n < numImgs; n++, pimg += (size_t)CC * HWB) {
        const float px = th[n][0] * gx + th[n][1] * gy + th[n][2];
        const float py = th[n][3] * gx + th[n][4] * gy + th[n][5];
        const float fx0 = floorf(px);
        const float fy0 = floorf(py);
        const float wx = px - fx0;
        const float wy = py - fy0;
        const int ix0 = (int)fx0;
        const int iy0 = (int)fy0;
        const int ix1 = ix0 + 1;
        const int iy1 = iy0 + 1;

        const bool vx0 = (ix0 >= 0) & (ix0 < WW);
        const bool vx1 = (ix1 >= 0) & (ix1 < WW);
        const bool vy0 = (iy0 >= 0) & (iy0 < HH);
        const bool vy1 = (iy1 >= 0) & (iy1 < HH);
        const bool inb = (vx0 | vx1) & (vy0 | vy1);

        // Warp-uniform skip only when the WHOLE warp is fully outside.
        if (__all_sync(FULL, !inb)) {
            oobVal = 0.0f;          // zeros padding still joins the max
            continue;
        }

        // For individually-OOB lanes all four weights are 0 -> val = 0,
        // which is exactly the zeros-padding value joining the max.
        const float w00 = (1.0f - wx) * (1.0f - wy) * (float)(vx0 && vy0);
        const float w01 = wx * (1.0f - wy) * (float)(vx1 && vy0);
        const float w10 = (1.0f - wx) * wy * (float)(vx0 && vy1);
        const float w11 = wx * wy * (float)(vx1 && vy1);

        const int ix0c = min(max(ix0, 0), WW - 1);
        const int ix1c = min(max(ix1, 0), WW - 1);
        const int iy0c = min(max(iy0, 0), HH - 1);
        const int iy1c = min(max(iy1, 0), HH - 1);

        const int o00 = iy0c * WW + ix0c;
        const int o01 = iy0c * WW + ix1c;
        const int o10 = iy1c * WW + ix0c;
        const int o11 = iy1c * WW + ix1c;

        // Full-offset (row AND column) match tests, per row pair.
        const int nbr00 = __shfl_down_sync(FULL, o00, 1);
        const int nbr10 = __shfl_down_sync(FULL, o10, 1);
        const bool need01 = (lane == 31) || (nbr00 != o01);
        const bool need11 = (lane == 31) || (nbr10 != o11);

        const char* a00 = pimg + (unsigned)(o00 * 4);
        const char* a10 = pimg + (unsigned)(o10 * 4);
        const char* a01 = pimg + (unsigned)(o01 * 4);
        const char* a11 = pimg + (unsigned)(o11 * 4);

#pragma unroll
        for (int half = 0; half < 2; half++) {
            const int cbase = half * 4;
            float v00[4], v10[4];
#pragma unroll
            for (int c = 0; c < 4; c++) {
                const int cc = cbase + c;
                v00[c] = __ldg((const float*)(a00 + cc * HWB));
                v10[c] = __ldg((const float*)(a10 + cc * HWB));
            }
#pragma unroll
            for (int c = 0; c < 4; c++) {
                const int cc = cbase + c;
                float v01 = __shfl_down_sync(FULL, v00[c], 1);
                float v11 = __shfl_down_sync(FULL, v10[c], 1);
                if (need01) v01 = __ldg((const float*)(a01 + cc * HWB));
                if (need11) v11 = __ldg((const float*)(a11 + cc * HWB));
                const float val = w00 * v00[c] + w01 * v01
                                + w10 * v10[c] + w11 * v11;
                acc[cbase + c] = fmaxf(acc[cbase + c], val);
            }
        }
    }

    if (active) {
        float* ob = out + ((size_t)(b * CC + cg * CPT)) * HW + pix;
#pragma unroll
        for (int c = 0; c < CPT; c++) ob[c * HW] = fmaxf(acc[c], oobVal);
    }
}

extern "C" void kernel_launch(void* const* d_in, const int* in_sizes, int n_in,
                              void* d_out, int out_size) {
    const float* x   = (const float*)d_in[0];
    // d_in[1] = rm (unused), d_in[3] = time_diffs (unused)
    const float* ptm = (const float*)d_in[2];
    const int*   rl  = (const int*)d_in[4];
    float* out = (float*)d_out;

    constexpr int HW = HH * WW;
    dim3 block(TPB);
    dim3 grid((HW + TPB - 1) / TPB, CC / CPT, BB);
    raindrop_fuse_kernel<<<grid, block>>>(x, ptm, rl, out);
}